// round 1
// baseline (speedup 1.0000x reference)
#include <cuda_runtime.h>
#include <math.h>

// Problem constants
#define NB   2
#define NS   1024
#define ND   1024
#define NH   16
#define NDH  64
#define NL   12
#define NHID 2816
#define NV   50257
#define MTOK 2048   // NB*NS

// ---------------- scratch buffers (device globals; no allocation) ----------
__device__ float g_x[MTOK * ND];        // residual stream
__device__ float g_h[MTOK * ND];        // rmsnorm output
__device__ float g_qkv[MTOK * 3 * ND];  // qkv
__device__ float g_y[MTOK * ND];        // attention output
__device__ float g_gate[MTOK * NHID];   // gate / activation

// ---------------- embedding ----------------
__global__ void embed_kernel(const int* __restrict__ idx,
                             const float* __restrict__ wte,
                             const float* __restrict__ wpe,
                             float* __restrict__ x) {
    int row = blockIdx.x;                 // 0..2047
    int t = threadIdx.x;                  // 0..255 -> one float4 each
    int tok = idx[row];
    int spos = row & (NS - 1);
    float4 a = ((const float4*)(wte + (size_t)tok * ND))[t];
    float4 b = ((const float4*)(wpe + (size_t)spos * ND))[t];
    float4 o;
    o.x = a.x + b.x; o.y = a.y + b.y; o.z = a.z + b.z; o.w = a.w + b.w;
    ((float4*)(x + (size_t)row * ND))[t] = o;
}

// ---------------- rmsnorm ----------------
__global__ void rmsnorm_kernel(const float* __restrict__ in,
                               const float* __restrict__ gamma,
                               float* __restrict__ out) {
    int row = blockIdx.x;
    int t = threadIdx.x;   // 256 threads, one float4 each (D=1024)
    float4 v = ((const float4*)(in + (size_t)row * ND))[t];
    float ss = v.x * v.x + v.y * v.y + v.z * v.z + v.w * v.w;
    #pragma unroll
    for (int off = 16; off; off >>= 1)
        ss += __shfl_xor_sync(0xFFFFFFFFu, ss, off);
    __shared__ float red[8];
    if ((t & 31) == 0) red[t >> 5] = ss;
    __syncthreads();
    float tot = red[0] + red[1] + red[2] + red[3] +
                red[4] + red[5] + red[6] + red[7];
    float r = rsqrtf(tot * (1.0f / (float)ND) + 1e-12f);
    float4 g = ((const float4*)gamma)[t];
    float4 o;
    o.x = v.x * r * g.x; o.y = v.y * r * g.y;
    o.z = v.z * r * g.z; o.w = v.w * r * g.w;
    ((float4*)(out + (size_t)row * ND))[t] = o;
}

// ---------------- tiled fp32 GEMM with fused epilogues ----------------
// C[M,N] = epi(A[M,K] @ B[K,N])
// EPI 0: C = acc
// EPI 1: C = X + acc            (residual add; X may alias C)
// EPI 2: C = silu(X) * acc      (SwiGLU; X may alias C)
template<int EPI>
__global__ __launch_bounds__(256)
void gemm_kernel(const float* __restrict__ A, const float* __restrict__ B,
                 const float* __restrict__ X, float* __restrict__ C,
                 int M, int N, int K) {
    __shared__ float As[16][132];   // transposed A tile, padded
    __shared__ float Bs[16][128];
    const int tid = threadIdx.x;
    const int tx = tid & 15;        // N direction
    const int ty = tid >> 4;        // M direction
    const int m0 = blockIdx.y * 128;
    const int n0 = blockIdx.x * 128;

    float acc[8][8];
    #pragma unroll
    for (int i = 0; i < 8; i++)
        #pragma unroll
        for (int j = 0; j < 8; j++) acc[i][j] = 0.0f;

    for (int k0 = 0; k0 < K; k0 += 16) {
        // Load A tile 128x16 (float4), store transposed
        #pragma unroll
        for (int i = 0; i < 2; i++) {
            int li = tid + i * 256;      // 0..511
            int r  = li >> 2;            // 0..127
            int c4 = (li & 3) * 4;       // 0,4,8,12
            float4 v = *(const float4*)(A + (size_t)(m0 + r) * K + k0 + c4);
            As[c4 + 0][r] = v.x; As[c4 + 1][r] = v.y;
            As[c4 + 2][r] = v.z; As[c4 + 3][r] = v.w;
        }
        // Load B tile 16x128 (scalar, col-guarded: N may be 50257)
        #pragma unroll
        for (int i = 0; i < 8; i++) {
            int li = tid + i * 256;      // 0..2047
            int r  = li >> 7;            // 0..15
            int c  = li & 127;
            int n  = n0 + c;
            Bs[r][c] = (n < N) ? B[(size_t)(k0 + r) * N + n] : 0.0f;
        }
        __syncthreads();
        #pragma unroll
        for (int kk = 0; kk < 16; kk++) {
            float af[8], bf[8];
            *(float4*)&af[0] = *(const float4*)&As[kk][ty * 8];
            *(float4*)&af[4] = *(const float4*)&As[kk][ty * 8 + 4];
            *(float4*)&bf[0] = *(const float4*)&Bs[kk][tx * 8];
            *(float4*)&bf[4] = *(const float4*)&Bs[kk][tx * 8 + 4];
            #pragma unroll
            for (int i = 0; i < 8; i++)
                #pragma unroll
                for (int j = 0; j < 8; j++)
                    acc[i][j] += af[i] * bf[j];
        }
        __syncthreads();
    }

    #pragma unroll
    for (int i = 0; i < 8; i++) {
        int m = m0 + ty * 8 + i;
        #pragma unroll
        for (int j = 0; j < 8; j++) {
            int n = n0 + tx * 8 + j;
            if (n < N) {
                size_t o = (size_t)m * N + n;
                if (EPI == 0) {
                    C[o] = acc[i][j];
                } else if (EPI == 1) {
                    C[o] = X[o] + acc[i][j];
                } else {
                    float gv = X[o];
                    float sig = 1.0f / (1.0f + __expf(-gv));
                    C[o] = gv * sig * acc[i][j];
                }
            }
        }
    }
}

// ---------------- flash attention (causal, fp32) ----------------
// grid (NB*NH, NS/128), block 128: one q-row per thread.
__global__ __launch_bounds__(128)
void attn_kernel(const float* __restrict__ qkv, float* __restrict__ y) {
    const int bh = blockIdx.x;           // 0..31
    const int b  = bh >> 4;
    const int hh = bh & 15;
    const int qy = blockIdx.y;           // 0..7
    const int tid = threadIdx.x;
    const int qrow = qy * 128 + tid;

    const float* qptr = qkv + ((size_t)(b * NS + qrow) * (3 * ND)) + hh * NDH;
    float q[NDH];
    #pragma unroll
    for (int i = 0; i < 16; i++)
        *(float4*)&q[i * 4] = *(const float4*)(qptr + i * 4);

    float o[NDH];
    #pragma unroll
    for (int d = 0; d < NDH; d++) o[d] = 0.0f;
    float m = -1e30f, l = 0.0f;

    __shared__ float ksm[64][64];
    __shared__ float vsm[64][64];

    const int ntiles = (qy + 1) * 2;     // 64-key tiles up to the diagonal
    for (int kt = 0; kt < ntiles; kt++) {
        const int kbase = kt * 64;
        // cooperative load of K,V tiles (64x64 each)
        #pragma unroll
        for (int i = 0; i < 8; i++) {
            int li = tid + i * 128;       // 0..1023
            int r  = li >> 4;             // 0..63
            int c4 = (li & 15) * 4;
            const float* base = qkv + ((size_t)(b * NS + kbase + r) * (3 * ND))
                                + hh * NDH + c4;
            *(float4*)&ksm[r][c4] = *(const float4*)(base + ND);
            *(float4*)&vsm[r][c4] = *(const float4*)(base + 2 * ND);
        }
        __syncthreads();

        if (qrow >= kbase) {
            #pragma unroll 1
            for (int jt = 0; jt < 4; jt++) {
                float s[16];
                #pragma unroll
                for (int j = 0; j < 16; j++) {
                    int key = kbase + jt * 16 + j;
                    if (key <= qrow) {
                        float a = 0.0f;
                        const float4* kr = (const float4*)ksm[jt * 16 + j];
                        #pragma unroll
                        for (int d4 = 0; d4 < 16; d4++) {
                            float4 kv = kr[d4];
                            a += q[d4 * 4 + 0] * kv.x + q[d4 * 4 + 1] * kv.y
                               + q[d4 * 4 + 2] * kv.z + q[d4 * 4 + 3] * kv.w;
                        }
                        s[j] = a * 0.125f;   // 1/sqrt(64)
                    } else {
                        s[j] = -1e30f;
                    }
                }
                float tm = s[0];
                #pragma unroll
                for (int j = 1; j < 16; j++) tm = fmaxf(tm, s[j]);
                float mnew = fmaxf(m, tm);
                float corr = __expf(m - mnew);
                float psum = 0.0f;
                #pragma unroll
                for (int j = 0; j < 16; j++) {
                    s[j] = __expf(s[j] - mnew);
                    psum += s[j];
                }
                l = l * corr + psum;
                m = mnew;
                #pragma unroll
                for (int d = 0; d < NDH; d++) o[d] *= corr;
                #pragma unroll
                for (int j = 0; j < 16; j++) {
                    float p = s[j];
                    const float4* vr = (const float4*)vsm[jt * 16 + j];
                    #pragma unroll
                    for (int d4 = 0; d4 < 16; d4++) {
                        float4 vv = vr[d4];
                        o[d4 * 4 + 0] += p * vv.x;
                        o[d4 * 4 + 1] += p * vv.y;
                        o[d4 * 4 + 2] += p * vv.z;
                        o[d4 * 4 + 3] += p * vv.w;
                    }
                }
            }
        }
        __syncthreads();
    }

    float inv = 1.0f / l;
    float* yp = y + ((size_t)(b * NS + qrow) * ND) + hh * NDH;
    #pragma unroll
    for (int i = 0; i < 16; i++) {
        float4 st;
        st.x = o[i * 4 + 0] * inv; st.y = o[i * 4 + 1] * inv;
        st.z = o[i * 4 + 2] * inv; st.w = o[i * 4 + 3] * inv;
        *(float4*)(yp + i * 4) = st;
    }
}

// ---------------- launch ----------------
extern "C" void kernel_launch(void* const* d_in, const int* in_sizes, int n_in,
                              void* d_out, int out_size) {
    const int*   idx   = (const int*)  d_in[0];
    const float* wte   = (const float*)d_in[1];
    const float* wpe   = (const float*)d_in[2];
    const float* g1    = (const float*)d_in[3];
    const float* Wqkv  = (const float*)d_in[4];
    const float* Wproj = (const float*)d_in[5];
    const float* g2    = (const float*)d_in[6];
    const float* Wg    = (const float*)d_in[7];
    const float* Wu    = (const float*)d_in[8];
    const float* Wd    = (const float*)d_in[9];
    const float* gf    = (const float*)d_in[10];
    const float* Wlm   = (const float*)d_in[11];
    float* out = (float*)d_out;

    float *px, *ph, *pqkv, *py, *pg;
    cudaGetSymbolAddress((void**)&px,   g_x);
    cudaGetSymbolAddress((void**)&ph,   g_h);
    cudaGetSymbolAddress((void**)&pqkv, g_qkv);
    cudaGetSymbolAddress((void**)&py,   g_y);
    cudaGetSymbolAddress((void**)&pg,   g_gate);

    embed_kernel<<<MTOK, 256>>>(idx, wte, wpe, px);

    for (int l = 0; l < NL; l++) {
        rmsnorm_kernel<<<MTOK, 256>>>(px, g1 + (size_t)l * ND, ph);
        gemm_kernel<0><<<dim3(3 * ND / 128, MTOK / 128), 256>>>(
            ph, Wqkv + (size_t)l * ND * 3 * ND, nullptr, pqkv, MTOK, 3 * ND, ND);
        attn_kernel<<<dim3(NB * NH, NS / 128), 128>>>(pqkv, py);
        gemm_kernel<1><<<dim3(ND / 128, MTOK / 128), 256>>>(
            py, Wproj + (size_t)l * ND * ND, px, px, MTOK, ND, ND);
        rmsnorm_kernel<<<MTOK, 256>>>(px, g2 + (size_t)l * ND, ph);
        gemm_kernel<0><<<dim3(NHID / 128, MTOK / 128), 256>>>(
            ph, Wg + (size_t)l * ND * NHID, nullptr, pg, MTOK, NHID, ND);
        gemm_kernel<2><<<dim3(NHID / 128, MTOK / 128), 256>>>(
            ph, Wu + (size_t)l * ND * NHID, pg, pg, MTOK, NHID, ND);
        gemm_kernel<1><<<dim3(ND / 128, MTOK / 128), 256>>>(
            pg, Wd + (size_t)l * NHID * ND, px, px, MTOK, ND, NHID);
    }

    rmsnorm_kernel<<<MTOK, 256>>>(px, gf, ph);
    gemm_kernel<0><<<dim3((NV + 127) / 128, MTOK / 128), 256>>>(
        ph, Wlm, nullptr, out, MTOK, NV, ND);
}

// round 3
// speedup vs baseline: 1.2079x; 1.2079x over previous
#include <cuda_runtime.h>
#include <math.h>
#include <stdint.h>

// Problem constants
#define NB   2
#define NS   1024
#define ND   1024
#define NH   16
#define NDH  64
#define NL   12
#define NHID 2816
#define NV   50257
#define MTOK 2048   // NB*NS

// GEMM tiling
#define BM 128
#define BN 128
#define BK 16
#define APAD 20    // As row stride (floats)
#define BPAD 136   // Bs row stride (floats)
#define ASZ (BM * APAD)   // 2560 floats
#define BSZ (BK * BPAD)   // 2176 floats
#define SMEM_FLOATS (4 * ASZ + 4 * BSZ)   // 18944 floats = 75776 B

// ---------------- scratch buffers (device globals; no allocation) ----------
__device__ float g_x[MTOK * ND];        // residual stream
__device__ float g_h[MTOK * ND];        // rmsnorm output
__device__ float g_qkv[MTOK * 3 * ND];  // qkv
__device__ float g_y[MTOK * ND];        // attention output
__device__ float g_gate[MTOK * NHID];   // gate / activation

// ---------------- helpers ----------------
__device__ __forceinline__ float tf32r(float x) {
    uint32_t u;
    asm("cvt.rna.tf32.f32 %0, %1;" : "=r"(u) : "f"(x));
    return __uint_as_float(u);
}

// ---------------- embedding ----------------
__global__ void embed_kernel(const int* __restrict__ idx,
                             const float* __restrict__ wte,
                             const float* __restrict__ wpe,
                             float* __restrict__ x) {
    int row = blockIdx.x;
    int t = threadIdx.x;
    int tok = idx[row];
    int spos = row & (NS - 1);
    float4 a = ((const float4*)(wte + (size_t)tok * ND))[t];
    float4 b = ((const float4*)(wpe + (size_t)spos * ND))[t];
    float4 o;
    o.x = a.x + b.x; o.y = a.y + b.y; o.z = a.z + b.z; o.w = a.w + b.w;
    ((float4*)(x + (size_t)row * ND))[t] = o;
}

// ---------------- rmsnorm ----------------
__global__ void rmsnorm_kernel(const float* __restrict__ in,
                               const float* __restrict__ gamma,
                               float* __restrict__ out) {
    int row = blockIdx.x;
    int t = threadIdx.x;
    float4 v = ((const float4*)(in + (size_t)row * ND))[t];
    float ss = v.x * v.x + v.y * v.y + v.z * v.z + v.w * v.w;
    #pragma unroll
    for (int off = 16; off; off >>= 1)
        ss += __shfl_xor_sync(0xFFFFFFFFu, ss, off);
    __shared__ float red[8];
    if ((t & 31) == 0) red[t >> 5] = ss;
    __syncthreads();
    float tot = red[0] + red[1] + red[2] + red[3] +
                red[4] + red[5] + red[6] + red[7];
    float r = rsqrtf(tot * (1.0f / (float)ND) + 1e-12f);
    float4 g = ((const float4*)gamma)[t];
    float4 o;
    o.x = v.x * r * g.x; o.y = v.y * r * g.y;
    o.z = v.z * r * g.z; o.w = v.w * r * g.w;
    ((float4*)(out + (size_t)row * ND))[t] = o;
}

// ---------------- 3xTF32 tensor-core GEMM with fused epilogues ----------------
// C[M,N] = epi(A[M,K] @ B[K,N])
// EPI 0: C = acc ; EPI 1: C = X + acc ; EPI 2: C = silu(X) * acc
// NG: N-bound guard + scalar B loads (LM head, N=50257)
template<int EPI, bool NG>
__global__ __launch_bounds__(256, 2)
void gemm_tc(const float* __restrict__ A, const float* __restrict__ B,
             const float* __restrict__ X, float* __restrict__ C,
             int M, int N, int K) {
    extern __shared__ float smem[];
    // layout: As_hi[2] | As_lo[2] | Bs_hi[2] | Bs_lo[2]
    float* Ah[2] = { smem,            smem + ASZ };
    float* Al[2] = { smem + 2 * ASZ,  smem + 3 * ASZ };
    float* Bh[2] = { smem + 4 * ASZ,            smem + 4 * ASZ + BSZ };
    float* Bl[2] = { smem + 4 * ASZ + 2 * BSZ,  smem + 4 * ASZ + 3 * BSZ };

    const int tid  = threadIdx.x;
    const int lane = tid & 31;
    const int warp = tid >> 5;
    const int wm = warp & 3;        // 0..3  (m dir)
    const int wn = warp >> 2;       // 0..1  (n dir)
    const int lq = lane >> 2;       // 0..7
    const int lr = lane & 3;        // 0..3
    const int m0 = blockIdx.y * BM;
    const int n0 = blockIdx.x * BN;

    float c[2][8][4];
    #pragma unroll
    for (int i = 0; i < 2; i++)
        #pragma unroll
        for (int j = 0; j < 8; j++)
            #pragma unroll
            for (int k = 0; k < 4; k++) c[i][j][k] = 0.0f;

    // global load indexing
    const int ar0 = tid >> 2;                 // 0..63
    const int ar1 = ar0 + 64;                 // 64..127
    const int ac  = (tid & 3) * 4;            // 0,4,8,12
    const int br0 = tid >> 5;                 // 0..7
    const int br1 = br0 + 8;                  // 8..15
    const int bc  = (tid & 31) * 4;           // 0..124

    float4 aS0, aS1;
    float bS0[4], bS1[4];

    auto gload = [&](int k0) {
        aS0 = *(const float4*)(A + (size_t)(m0 + ar0) * K + k0 + ac);
        aS1 = *(const float4*)(A + (size_t)(m0 + ar1) * K + k0 + ac);
        if (!NG) {
            *(float4*)bS0 = *(const float4*)(B + (size_t)(k0 + br0) * N + n0 + bc);
            *(float4*)bS1 = *(const float4*)(B + (size_t)(k0 + br1) * N + n0 + bc);
        } else {
            #pragma unroll
            for (int j = 0; j < 4; j++) {
                int n = n0 + bc + j;
                bS0[j] = (n < N) ? B[(size_t)(k0 + br0) * N + n] : 0.0f;
                bS1[j] = (n < N) ? B[(size_t)(k0 + br1) * N + n] : 0.0f;
            }
        }
    };

    // split x into hi (tf32) + lo (tf32 of residual) and store both
    auto sstore = [&](int buf) {
        float4 h, l;
        h.x = tf32r(aS0.x); l.x = tf32r(aS0.x - h.x);
        h.y = tf32r(aS0.y); l.y = tf32r(aS0.y - h.y);
        h.z = tf32r(aS0.z); l.z = tf32r(aS0.z - h.z);
        h.w = tf32r(aS0.w); l.w = tf32r(aS0.w - h.w);
        *(float4*)(Ah[buf] + ar0 * APAD + ac) = h;
        *(float4*)(Al[buf] + ar0 * APAD + ac) = l;
        h.x = tf32r(aS1.x); l.x = tf32r(aS1.x - h.x);
        h.y = tf32r(aS1.y); l.y = tf32r(aS1.y - h.y);
        h.z = tf32r(aS1.z); l.z = tf32r(aS1.z - h.z);
        h.w = tf32r(aS1.w); l.w = tf32r(aS1.w - h.w);
        *(float4*)(Ah[buf] + ar1 * APAD + ac) = h;
        *(float4*)(Al[buf] + ar1 * APAD + ac) = l;
        h.x = tf32r(bS0[0]); l.x = tf32r(bS0[0] - h.x);
        h.y = tf32r(bS0[1]); l.y = tf32r(bS0[1] - h.y);
        h.z = tf32r(bS0[2]); l.z = tf32r(bS0[2] - h.z);
        h.w = tf32r(bS0[3]); l.w = tf32r(bS0[3] - h.w);
        *(float4*)(Bh[buf] + br0 * BPAD + bc) = h;
        *(float4*)(Bl[buf] + br0 * BPAD + bc) = l;
        h.x = tf32r(bS1[0]); l.x = tf32r(bS1[0] - h.x);
        h.y = tf32r(bS1[1]); l.y = tf32r(bS1[1] - h.y);
        h.z = tf32r(bS1[2]); l.z = tf32r(bS1[2] - h.z);
        h.w = tf32r(bS1[3]); l.w = tf32r(bS1[3] - h.w);
        *(float4*)(Bh[buf] + br1 * BPAD + bc) = h;
        *(float4*)(Bl[buf] + br1 * BPAD + bc) = l;
    };

    #define MMA_TF32(acc, a, b0, b1)                                         \
        asm volatile(                                                         \
            "mma.sync.aligned.m16n8k8.row.col.f32.tf32.tf32.f32 "             \
            "{%0,%1,%2,%3}, {%4,%5,%6,%7}, {%8,%9}, {%0,%1,%2,%3};"           \
            : "+f"(acc[0]), "+f"(acc[1]), "+f"(acc[2]), "+f"(acc[3])          \
            : "r"(a[0]), "r"(a[1]), "r"(a[2]), "r"(a[3]), "r"(b0), "r"(b1))

    auto compute = [&](int buf) {
        const float* aph = Ah[buf];
        const float* apl = Al[buf];
        const float* bph = Bh[buf];
        const float* bpl = Bl[buf];
        #pragma unroll
        for (int ks = 0; ks < 2; ks++) {
            const int k0 = ks * 8;
            uint32_t ah[2][4], al[2][4];
            #pragma unroll
            for (int mf = 0; mf < 2; mf++) {
                int rb = wm * 32 + mf * 16 + lq;
                ah[mf][0] = __float_as_uint(aph[rb * APAD + k0 + lr]);
                ah[mf][1] = __float_as_uint(aph[(rb + 8) * APAD + k0 + lr]);
                ah[mf][2] = __float_as_uint(aph[rb * APAD + k0 + 4 + lr]);
                ah[mf][3] = __float_as_uint(aph[(rb + 8) * APAD + k0 + 4 + lr]);
                al[mf][0] = __float_as_uint(apl[rb * APAD + k0 + lr]);
                al[mf][1] = __float_as_uint(apl[(rb + 8) * APAD + k0 + lr]);
                al[mf][2] = __float_as_uint(apl[rb * APAD + k0 + 4 + lr]);
                al[mf][3] = __float_as_uint(apl[(rb + 8) * APAD + k0 + 4 + lr]);
            }
            #pragma unroll
            for (int nf = 0; nf < 8; nf++) {
                int col = wn * 64 + nf * 8 + lq;
                uint32_t bh0 = __float_as_uint(bph[(k0 + lr) * BPAD + col]);
                uint32_t bh1 = __float_as_uint(bph[(k0 + 4 + lr) * BPAD + col]);
                uint32_t bl0 = __float_as_uint(bpl[(k0 + lr) * BPAD + col]);
                uint32_t bl1 = __float_as_uint(bpl[(k0 + 4 + lr) * BPAD + col]);
                #pragma unroll
                for (int mf = 0; mf < 2; mf++) {
                    MMA_TF32(c[mf][nf], ah[mf], bh0, bh1);   // hi*hi
                    MMA_TF32(c[mf][nf], ah[mf], bl0, bl1);   // hi*lo
                    MMA_TF32(c[mf][nf], al[mf], bh0, bh1);   // lo*hi
                }
            }
        }
    };

    // ---- main loop: double smem buffer, one sync per iter ----
    gload(0);
    sstore(0);
    __syncthreads();
    int cur = 0;
    for (int k0 = 0; k0 < K; k0 += BK) {
        int nk = k0 + BK;
        if (nk < K) gload(nk);
        compute(cur);
        if (nk < K) {
            sstore(cur ^ 1);
            __syncthreads();
            cur ^= 1;
        }
    }

    // ---- epilogue ----
    #pragma unroll
    for (int mf = 0; mf < 2; mf++) {
        int r0 = m0 + wm * 32 + mf * 16 + lq;
        int r1 = r0 + 8;
        #pragma unroll
        for (int nf = 0; nf < 8; nf++) {
            int col = n0 + wn * 64 + nf * 8 + 2 * lr;
            if (!NG) {
                size_t o0 = (size_t)r0 * N + col;
                size_t o1 = (size_t)r1 * N + col;
                float2 v0 = make_float2(c[mf][nf][0], c[mf][nf][1]);
                float2 v1 = make_float2(c[mf][nf][2], c[mf][nf][3]);
                if (EPI == 1) {
                    float2 x0 = *(const float2*)(X + o0);
                    float2 x1 = *(const float2*)(X + o1);
                    v0.x += x0.x; v0.y += x0.y; v1.x += x1.x; v1.y += x1.y;
                } else if (EPI == 2) {
                    float2 x0 = *(const float2*)(X + o0);
                    float2 x1 = *(const float2*)(X + o1);
                    v0.x *= x0.x / (1.0f + __expf(-x0.x));
                    v0.y *= x0.y / (1.0f + __expf(-x0.y));
                    v1.x *= x1.x / (1.0f + __expf(-x1.x));
                    v1.y *= x1.y / (1.0f + __expf(-x1.y));
                }
                *(float2*)(C + o0) = v0;
                *(float2*)(C + o1) = v1;
            } else {
                #pragma unroll
                for (int e = 0; e < 2; e++) {
                    int n = col + e;
                    if (n < N) {
                        size_t o0 = (size_t)r0 * N + n;
                        size_t o1 = (size_t)r1 * N + n;
                        float v0 = c[mf][nf][e];
                        float v1 = c[mf][nf][2 + e];
                        if (EPI == 1) { v0 += X[o0]; v1 += X[o1]; }
                        else if (EPI == 2) {
                            float x0 = X[o0], x1 = X[o1];
                            v0 *= x0 / (1.0f + __expf(-x0));
                            v1 *= x1 / (1.0f + __expf(-x1));
                        }
                        C[o0] = v0; C[o1] = v1;
                    }
                }
            }
        }
    }
    #undef MMA_TF32
}

// ---------------- flash attention (causal, fp32) ----------------
__global__ __launch_bounds__(128)
void attn_kernel(const float* __restrict__ qkv, float* __restrict__ y) {
    const int bh = blockIdx.x;
    const int b  = bh >> 4;
    const int hh = bh & 15;
    const int qy = blockIdx.y;
    const int tid = threadIdx.x;
    const int qrow = qy * 128 + tid;

    const float* qptr = qkv + ((size_t)(b * NS + qrow) * (3 * ND)) + hh * NDH;
    float q[NDH];
    #pragma unroll
    for (int i = 0; i < 16; i++)
        *(float4*)&q[i * 4] = *(const float4*)(qptr + i * 4);

    float o[NDH];
    #pragma unroll
    for (int d = 0; d < NDH; d++) o[d] = 0.0f;
    float m = -1e30f, l = 0.0f;

    __shared__ float ksm[64][64];
    __shared__ float vsm[64][64];

    const int ntiles = (qy + 1) * 2;
    for (int kt = 0; kt < ntiles; kt++) {
        const int kbase = kt * 64;
        #pragma unroll
        for (int i = 0; i < 8; i++) {
            int li = tid + i * 128;
            int r  = li >> 4;
            int c4 = (li & 15) * 4;
            const float* base = qkv + ((size_t)(b * NS + kbase + r) * (3 * ND))
                                + hh * NDH + c4;
            *(float4*)&ksm[r][c4] = *(const float4*)(base + ND);
            *(float4*)&vsm[r][c4] = *(const float4*)(base + 2 * ND);
        }
        __syncthreads();

        if (qrow >= kbase) {
            #pragma unroll 1
            for (int jt = 0; jt < 4; jt++) {
                float s[16];
                #pragma unroll
                for (int j = 0; j < 16; j++) {
                    int key = kbase + jt * 16 + j;
                    if (key <= qrow) {
                        float a = 0.0f;
                        const float4* kr = (const float4*)ksm[jt * 16 + j];
                        #pragma unroll
                        for (int d4 = 0; d4 < 16; d4++) {
                            float4 kv = kr[d4];
                            a += q[d4 * 4 + 0] * kv.x + q[d4 * 4 + 1] * kv.y
                               + q[d4 * 4 + 2] * kv.z + q[d4 * 4 + 3] * kv.w;
                        }
                        s[j] = a * 0.125f;
                    } else {
                        s[j] = -1e30f;
                    }
                }
                float tm = s[0];
                #pragma unroll
                for (int j = 1; j < 16; j++) tm = fmaxf(tm, s[j]);
                float mnew = fmaxf(m, tm);
                float corr = __expf(m - mnew);
                float psum = 0.0f;
                #pragma unroll
                for (int j = 0; j < 16; j++) {
                    s[j] = __expf(s[j] - mnew);
                    psum += s[j];
                }
                l = l * corr + psum;
                m = mnew;
                #pragma unroll
                for (int d = 0; d < NDH; d++) o[d] *= corr;
                #pragma unroll
                for (int j = 0; j < 16; j++) {
                    float p = s[j];
                    const float4* vr = (const float4*)vsm[jt * 16 + j];
                    #pragma unroll
                    for (int d4 = 0; d4 < 16; d4++) {
                        float4 vv = vr[d4];
                        o[d4 * 4 + 0] += p * vv.x;
                        o[d4 * 4 + 1] += p * vv.y;
                        o[d4 * 4 + 2] += p * vv.z;
                        o[d4 * 4 + 3] += p * vv.w;
                    }
                }
            }
        }
        __syncthreads();
    }

    float inv = 1.0f / l;
    float* yp = y + ((size_t)(b * NS + qrow) * ND) + hh * NDH;
    #pragma unroll
    for (int i = 0; i < 16; i++) {
        float4 st;
        st.x = o[i * 4 + 0] * inv; st.y = o[i * 4 + 1] * inv;
        st.z = o[i * 4 + 2] * inv; st.w = o[i * 4 + 3] * inv;
        *(float4*)(yp + i * 4) = st;
    }
}

// ---------------- launch ----------------
extern "C" void kernel_launch(void* const* d_in, const int* in_sizes, int n_in,
                              void* d_out, int out_size) {
    const int*   idx   = (const int*)  d_in[0];
    const float* wte   = (const float*)d_in[1];
    const float* wpe   = (const float*)d_in[2];
    const float* g1    = (const float*)d_in[3];
    const float* Wqkv  = (const float*)d_in[4];
    const float* Wproj = (const float*)d_in[5];
    const float* g2    = (const float*)d_in[6];
    const float* Wg    = (const float*)d_in[7];
    const float* Wu    = (const float*)d_in[8];
    const float* Wd    = (const float*)d_in[9];
    const float* gf    = (const float*)d_in[10];
    const float* Wlm   = (const float*)d_in[11];
    float* out = (float*)d_out;

    float *px, *ph, *pqkv, *py, *pg;
    cudaGetSymbolAddress((void**)&px,   g_x);
    cudaGetSymbolAddress((void**)&ph,   g_h);
    cudaGetSymbolAddress((void**)&pqkv, g_qkv);
    cudaGetSymbolAddress((void**)&py,   g_y);
    cudaGetSymbolAddress((void**)&pg,   g_gate);

    const int smem_bytes = SMEM_FLOATS * sizeof(float);  // 75776
    cudaFuncSetAttribute(gemm_tc<0, false>,
        cudaFuncAttributeMaxDynamicSharedMemorySize, smem_bytes);
    cudaFuncSetAttribute(gemm_tc<1, false>,
        cudaFuncAttributeMaxDynamicSharedMemorySize, smem_bytes);
    cudaFuncSetAttribute(gemm_tc<2, false>,
        cudaFuncAttributeMaxDynamicSharedMemorySize, smem_bytes);
    cudaFuncSetAttribute(gemm_tc<0, true>,
        cudaFuncAttributeMaxDynamicSharedMemorySize, smem_bytes);

    embed_kernel<<<MTOK, 256>>>(idx, wte, wpe, px);

    for (int l = 0; l < NL; l++) {
        rmsnorm_kernel<<<MTOK, 256>>>(px, g1 + (size_t)l * ND, ph);
        gemm_tc<0, false><<<dim3(3 * ND / 128, MTOK / 128), 256, smem_bytes>>>(
            ph, Wqkv + (size_t)l * ND * 3 * ND, nullptr, pqkv, MTOK, 3 * ND, ND);
        attn_kernel<<<dim3(NB * NH, NS / 128), 128>>>(pqkv, py);
        gemm_tc<1, false><<<dim3(ND / 128, MTOK / 128), 256, smem_bytes>>>(
            py, Wproj + (size_t)l * ND * ND, px, px, MTOK, ND, ND);
        rmsnorm_kernel<<<MTOK, 256>>>(px, g2 + (size_t)l * ND, ph);
        gemm_tc<0, false><<<dim3(NHID / 128, MTOK / 128), 256, smem_bytes>>>(
            ph, Wg + (size_t)l * ND * NHID, nullptr, pg, MTOK, NHID, ND);
        gemm_tc<2, false><<<dim3(NHID / 128, MTOK / 128), 256, smem_bytes>>>(
            ph, Wu + (size_t)l * ND * NHID, pg, pg, MTOK, NHID, ND);
        gemm_tc<1, false><<<dim3(ND / 128, MTOK / 128), 256, smem_bytes>>>(
            pg, Wd + (size_t)l * NHID * ND, px, px, MTOK, ND, NHID);
    }

    rmsnorm_kernel<<<MTOK, 256>>>(px, gf, ph);
    gemm_tc<0, true><<<dim3((NV + 127) / 128, MTOK / 128), 256, smem_bytes>>>(
        ph, Wlm, nullptr, out, MTOK, NV, ND);
}

// round 4
// speedup vs baseline: 1.2202x; 1.0102x over previous
#include <cuda_runtime.h>
#include <math.h>
#include <stdint.h>

// Problem constants
#define NB   2
#define NS   1024
#define ND   1024
#define NH   16
#define NDH  64
#define NL   12
#define NHID 2816
#define NV   50257
#define MTOK 2048   // NB*NS

// GEMM tiling
#define BM 128
#define BN 128
#define BK 16
#define APAD 20    // As row stride (floats)
#define BPAD 136   // Bs row stride (floats)
#define ASZ (BM * APAD)   // 2560 floats
#define BSZ (BK * BPAD)   // 2176 floats
#define SMEM_FLOATS (4 * ASZ + 4 * BSZ)   // 18944 floats = 75776 B

// ---------------- scratch buffers (device globals; no allocation) ----------
__device__ float g_x[MTOK * ND];        // residual stream
__device__ float g_h[MTOK * ND];        // rmsnorm output
__device__ float g_qkv[MTOK * 3 * ND];  // qkv
__device__ float g_y[MTOK * ND];        // attention output
__device__ float g_gate[MTOK * NHID];   // gate / activation

// ---------------- helpers ----------------
__device__ __forceinline__ float tf32r(float x) {
    uint32_t u;
    asm("cvt.rna.tf32.f32 %0, %1;" : "=r"(u) : "f"(x));
    return __uint_as_float(u);
}

// ---------------- embedding ----------------
__global__ void embed_kernel(const int* __restrict__ idx,
                             const float* __restrict__ wte,
                             const float* __restrict__ wpe,
                             float* __restrict__ x) {
    int row = blockIdx.x;
    int t = threadIdx.x;
    int tok = idx[row];
    int spos = row & (NS - 1);
    float4 a = ((const float4*)(wte + (size_t)tok * ND))[t];
    float4 b = ((const float4*)(wpe + (size_t)spos * ND))[t];
    float4 o;
    o.x = a.x + b.x; o.y = a.y + b.y; o.z = a.z + b.z; o.w = a.w + b.w;
    ((float4*)(x + (size_t)row * ND))[t] = o;
}

// ---------------- rmsnorm ----------------
__global__ void rmsnorm_kernel(const float* __restrict__ in,
                               const float* __restrict__ gamma,
                               float* __restrict__ out) {
    int row = blockIdx.x;
    int t = threadIdx.x;
    float4 v = ((const float4*)(in + (size_t)row * ND))[t];
    float ss = v.x * v.x + v.y * v.y + v.z * v.z + v.w * v.w;
    #pragma unroll
    for (int off = 16; off; off >>= 1)
        ss += __shfl_xor_sync(0xFFFFFFFFu, ss, off);
    __shared__ float red[8];
    if ((t & 31) == 0) red[t >> 5] = ss;
    __syncthreads();
    float tot = red[0] + red[1] + red[2] + red[3] +
                red[4] + red[5] + red[6] + red[7];
    float r = rsqrtf(tot * (1.0f / (float)ND) + 1e-12f);
    float4 g = ((const float4*)gamma)[t];
    float4 o;
    o.x = v.x * r * g.x; o.y = v.y * r * g.y;
    o.z = v.z * r * g.z; o.w = v.w * r * g.w;
    ((float4*)(out + (size_t)row * ND))[t] = o;
}

// ---------------- 3xTF32 tensor-core GEMM with fused epilogues ----------------
// C[M,N] = epi(A[M,K] @ B[K,N])
// EPI 0: C = acc ; EPI 1: C = X + acc ; EPI 2: C = silu(X) * acc
// NG: N-bound guard + scalar B loads (LM head, N=50257)
template<int EPI, bool NG>
__global__ __launch_bounds__(256, 2)
void gemm_tc(const float* __restrict__ A, const float* __restrict__ B,
             const float* __restrict__ X, float* __restrict__ C,
             int M, int N, int K) {
    extern __shared__ float smem[];
    // layout: As_hi[2] | As_lo[2] | Bs_hi[2] | Bs_lo[2]
    float* Ah[2] = { smem,            smem + ASZ };
    float* Al[2] = { smem + 2 * ASZ,  smem + 3 * ASZ };
    float* Bh[2] = { smem + 4 * ASZ,            smem + 4 * ASZ + BSZ };
    float* Bl[2] = { smem + 4 * ASZ + 2 * BSZ,  smem + 4 * ASZ + 3 * BSZ };

    const int tid  = threadIdx.x;
    const int lane = tid & 31;
    const int warp = tid >> 5;
    const int wm = warp & 3;        // 0..3  (m dir)
    const int wn = warp >> 2;       // 0..1  (n dir)
    const int lq = lane >> 2;       // 0..7
    const int lr = lane & 3;        // 0..3
    const int m0 = blockIdx.y * BM;
    const int n0 = blockIdx.x * BN;

    float c[2][8][4];
    #pragma unroll
    for (int i = 0; i < 2; i++)
        #pragma unroll
        for (int j = 0; j < 8; j++)
            #pragma unroll
            for (int k = 0; k < 4; k++) c[i][j][k] = 0.0f;

    // global load indexing
    const int ar0 = tid >> 2;                 // 0..63
    const int ar1 = ar0 + 64;                 // 64..127
    const int ac  = (tid & 3) * 4;            // 0,4,8,12
    const int br0 = tid >> 5;                 // 0..7
    const int br1 = br0 + 8;                  // 8..15
    const int bc  = (tid & 31) * 4;           // 0..124

    float4 aS0, aS1;
    float bS0[4], bS1[4];

    auto gload = [&](int k0) {
        aS0 = *(const float4*)(A + (size_t)(m0 + ar0) * K + k0 + ac);
        aS1 = *(const float4*)(A + (size_t)(m0 + ar1) * K + k0 + ac);
        if (!NG) {
            *(float4*)bS0 = *(const float4*)(B + (size_t)(k0 + br0) * N + n0 + bc);
            *(float4*)bS1 = *(const float4*)(B + (size_t)(k0 + br1) * N + n0 + bc);
        } else {
            #pragma unroll
            for (int j = 0; j < 4; j++) {
                int n = n0 + bc + j;
                bS0[j] = (n < N) ? B[(size_t)(k0 + br0) * N + n] : 0.0f;
                bS1[j] = (n < N) ? B[(size_t)(k0 + br1) * N + n] : 0.0f;
            }
        }
    };

    // split x into hi (tf32) + lo (tf32 of residual) and store both
    auto sstore = [&](int buf) {
        float4 h, l;
        h.x = tf32r(aS0.x); l.x = tf32r(aS0.x - h.x);
        h.y = tf32r(aS0.y); l.y = tf32r(aS0.y - h.y);
        h.z = tf32r(aS0.z); l.z = tf32r(aS0.z - h.z);
        h.w = tf32r(aS0.w); l.w = tf32r(aS0.w - h.w);
        *(float4*)(Ah[buf] + ar0 * APAD + ac) = h;
        *(float4*)(Al[buf] + ar0 * APAD + ac) = l;
        h.x = tf32r(aS1.x); l.x = tf32r(aS1.x - h.x);
        h.y = tf32r(aS1.y); l.y = tf32r(aS1.y - h.y);
        h.z = tf32r(aS1.z); l.z = tf32r(aS1.z - h.z);
        h.w = tf32r(aS1.w); l.w = tf32r(aS1.w - h.w);
        *(float4*)(Ah[buf] + ar1 * APAD + ac) = h;
        *(float4*)(Al[buf] + ar1 * APAD + ac) = l;
        h.x = tf32r(bS0[0]); l.x = tf32r(bS0[0] - h.x);
        h.y = tf32r(bS0[1]); l.y = tf32r(bS0[1] - h.y);
        h.z = tf32r(bS0[2]); l.z = tf32r(bS0[2] - h.z);
        h.w = tf32r(bS0[3]); l.w = tf32r(bS0[3] - h.w);
        *(float4*)(Bh[buf] + br0 * BPAD + bc) = h;
        *(float4*)(Bl[buf] + br0 * BPAD + bc) = l;
        h.x = tf32r(bS1[0]); l.x = tf32r(bS1[0] - h.x);
        h.y = tf32r(bS1[1]); l.y = tf32r(bS1[1] - h.y);
        h.z = tf32r(bS1[2]); l.z = tf32r(bS1[2] - h.z);
        h.w = tf32r(bS1[3]); l.w = tf32r(bS1[3] - h.w);
        *(float4*)(Bh[buf] + br1 * BPAD + bc) = h;
        *(float4*)(Bl[buf] + br1 * BPAD + bc) = l;
    };

    #define MMA_TF32(acc, a, b0, b1)                                         \
        asm volatile(                                                         \
            "mma.sync.aligned.m16n8k8.row.col.f32.tf32.tf32.f32 "             \
            "{%0,%1,%2,%3}, {%4,%5,%6,%7}, {%8,%9}, {%0,%1,%2,%3};"           \
            : "+f"(acc[0]), "+f"(acc[1]), "+f"(acc[2]), "+f"(acc[3])          \
            : "r"(a[0]), "r"(a[1]), "r"(a[2]), "r"(a[3]), "r"(b0), "r"(b1))

    auto compute = [&](int buf) {
        const float* aph = Ah[buf];
        const float* apl = Al[buf];
        const float* bph = Bh[buf];
        const float* bpl = Bl[buf];
        #pragma unroll
        for (int ks = 0; ks < 2; ks++) {
            const int k0 = ks * 8;
            uint32_t ah[2][4], al[2][4];
            #pragma unroll
            for (int mf = 0; mf < 2; mf++) {
                int rb = wm * 32 + mf * 16 + lq;
                ah[mf][0] = __float_as_uint(aph[rb * APAD + k0 + lr]);
                ah[mf][1] = __float_as_uint(aph[(rb + 8) * APAD + k0 + lr]);
                ah[mf][2] = __float_as_uint(aph[rb * APAD + k0 + 4 + lr]);
                ah[mf][3] = __float_as_uint(aph[(rb + 8) * APAD + k0 + 4 + lr]);
                al[mf][0] = __float_as_uint(apl[rb * APAD + k0 + lr]);
                al[mf][1] = __float_as_uint(apl[(rb + 8) * APAD + k0 + lr]);
                al[mf][2] = __float_as_uint(apl[rb * APAD + k0 + 4 + lr]);
                al[mf][3] = __float_as_uint(apl[(rb + 8) * APAD + k0 + 4 + lr]);
            }
            #pragma unroll
            for (int nf = 0; nf < 8; nf++) {
                int col = wn * 64 + nf * 8 + lq;
                uint32_t bh0 = __float_as_uint(bph[(k0 + lr) * BPAD + col]);
                uint32_t bh1 = __float_as_uint(bph[(k0 + 4 + lr) * BPAD + col]);
                uint32_t bl0 = __float_as_uint(bpl[(k0 + lr) * BPAD + col]);
                uint32_t bl1 = __float_as_uint(bpl[(k0 + 4 + lr) * BPAD + col]);
                #pragma unroll
                for (int mf = 0; mf < 2; mf++) {
                    MMA_TF32(c[mf][nf], ah[mf], bh0, bh1);   // hi*hi
                    MMA_TF32(c[mf][nf], ah[mf], bl0, bl1);   // hi*lo
                    MMA_TF32(c[mf][nf], al[mf], bh0, bh1);   // lo*hi
                }
            }
        }
    };

    // ---- main loop: double smem buffer, one sync per iter ----
    gload(0);
    sstore(0);
    __syncthreads();
    int cur = 0;
    for (int k0 = 0; k0 < K; k0 += BK) {
        int nk = k0 + BK;
        if (nk < K) gload(nk);
        compute(cur);
        if (nk < K) {
            sstore(cur ^ 1);
            __syncthreads();
            cur ^= 1;
        }
    }

    // ---- epilogue ----
    #pragma unroll
    for (int mf = 0; mf < 2; mf++) {
        int r0 = m0 + wm * 32 + mf * 16 + lq;
        int r1 = r0 + 8;
        #pragma unroll
        for (int nf = 0; nf < 8; nf++) {
            int col = n0 + wn * 64 + nf * 8 + 2 * lr;
            if (!NG) {
                size_t o0 = (size_t)r0 * N + col;
                size_t o1 = (size_t)r1 * N + col;
                float2 v0 = make_float2(c[mf][nf][0], c[mf][nf][1]);
                float2 v1 = make_float2(c[mf][nf][2], c[mf][nf][3]);
                if (EPI == 1) {
                    float2 x0 = *(const float2*)(X + o0);
                    float2 x1 = *(const float2*)(X + o1);
                    v0.x += x0.x; v0.y += x0.y; v1.x += x1.x; v1.y += x1.y;
                } else if (EPI == 2) {
                    float2 x0 = *(const float2*)(X + o0);
                    float2 x1 = *(const float2*)(X + o1);
                    v0.x *= x0.x / (1.0f + __expf(-x0.x));
                    v0.y *= x0.y / (1.0f + __expf(-x0.y));
                    v1.x *= x1.x / (1.0f + __expf(-x1.x));
                    v1.y *= x1.y / (1.0f + __expf(-x1.y));
                }
                *(float2*)(C + o0) = v0;
                *(float2*)(C + o1) = v1;
            } else {
                #pragma unroll
                for (int e = 0; e < 2; e++) {
                    int n = col + e;
                    if (n < N) {
                        size_t o0 = (size_t)r0 * N + n;
                        size_t o1 = (size_t)r1 * N + n;
                        float v0 = c[mf][nf][e];
                        float v1 = c[mf][nf][2 + e];
                        if (EPI == 1) { v0 += X[o0]; v1 += X[o1]; }
                        else if (EPI == 2) {
                            float x0 = X[o0], x1 = X[o1];
                            v0 *= x0 / (1.0f + __expf(-x0));
                            v1 *= x1 / (1.0f + __expf(-x1));
                        }
                        C[o0] = v0; C[o1] = v1;
                    }
                }
            }
        }
    }
    #undef MMA_TF32
}

// ---------------- flash attention (causal, fp32) ----------------
__global__ __launch_bounds__(128)
void attn_kernel(const float* __restrict__ qkv, float* __restrict__ y) {
    const int bh = blockIdx.x;
    const int b  = bh >> 4;
    const int hh = bh & 15;
    const int qy = blockIdx.y;
    const int tid = threadIdx.x;
    const int qrow = qy * 128 + tid;

    const float* qptr = qkv + ((size_t)(b * NS + qrow) * (3 * ND)) + hh * NDH;
    float q[NDH];
    #pragma unroll
    for (int i = 0; i < 16; i++)
        *(float4*)&q[i * 4] = *(const float4*)(qptr + i * 4);

    float o[NDH];
    #pragma unroll
    for (int d = 0; d < NDH; d++) o[d] = 0.0f;
    float m = -1e30f, l = 0.0f;

    __shared__ float ksm[64][64];
    __shared__ float vsm[64][64];

    const int ntiles = (qy + 1) * 2;
    for (int kt = 0; kt < ntiles; kt++) {
        const int kbase = kt * 64;
        #pragma unroll
        for (int i = 0; i < 8; i++) {
            int li = tid + i * 128;
            int r  = li >> 4;
            int c4 = (li & 15) * 4;
            const float* base = qkv + ((size_t)(b * NS + kbase + r) * (3 * ND))
                                + hh * NDH + c4;
            *(float4*)&ksm[r][c4] = *(const float4*)(base + ND);
            *(float4*)&vsm[r][c4] = *(const float4*)(base + 2 * ND);
        }
        __syncthreads();

        if (qrow >= kbase) {
            #pragma unroll 1
            for (int jt = 0; jt < 4; jt++) {
                float s[16];
                #pragma unroll
                for (int j = 0; j < 16; j++) {
                    int key = kbase + jt * 16 + j;
                    if (key <= qrow) {
                        float a = 0.0f;
                        const float4* kr = (const float4*)ksm[jt * 16 + j];
                        #pragma unroll
                        for (int d4 = 0; d4 < 16; d4++) {
                            float4 kv = kr[d4];
                            a += q[d4 * 4 + 0] * kv.x + q[d4 * 4 + 1] * kv.y
                               + q[d4 * 4 + 2] * kv.z + q[d4 * 4 + 3] * kv.w;
                        }
                        s[j] = a * 0.125f;
                    } else {
                        s[j] = -1e30f;
                    }
                }
                float tm = s[0];
                #pragma unroll
                for (int j = 1; j < 16; j++) tm = fmaxf(tm, s[j]);
                float mnew = fmaxf(m, tm);
                float corr = __expf(m - mnew);
                float psum = 0.0f;
                #pragma unroll
                for (int j = 0; j < 16; j++) {
                    s[j] = __expf(s[j] - mnew);
                    psum += s[j];
                }
                l = l * corr + psum;
                m = mnew;
                #pragma unroll
                for (int d = 0; d < NDH; d++) o[d] *= corr;
                #pragma unroll
                for (int j = 0; j < 16; j++) {
                    float p = s[j];
                    const float4* vr = (const float4*)vsm[jt * 16 + j];
                    #pragma unroll
                    for (int d4 = 0; d4 < 16; d4++) {
                        float4 vv = vr[d4];
                        o[d4 * 4 + 0] += p * vv.x;
                        o[d4 * 4 + 1] += p * vv.y;
                        o[d4 * 4 + 2] += p * vv.z;
                        o[d4 * 4 + 3] += p * vv.w;
                    }
                }
            }
        }
        __syncthreads();
    }

    float inv = 1.0f / l;
    float* yp = y + ((size_t)(b * NS + qrow) * ND) + hh * NDH;
    #pragma unroll
    for (int i = 0; i < 16; i++) {
        float4 st;
        st.x = o[i * 4 + 0] * inv; st.y = o[i * 4 + 1] * inv;
        st.z = o[i * 4 + 2] * inv; st.w = o[i * 4 + 3] * inv;
        *(float4*)(yp + i * 4) = st;
    }
}

// ---------------- launch ----------------
extern "C" void kernel_launch(void* const* d_in, const int* in_sizes, int n_in,
                              void* d_out, int out_size) {
    const int*   idx   = (const int*)  d_in[0];
    const float* wte   = (const float*)d_in[1];
    const float* wpe   = (const float*)d_in[2];
    const float* g1    = (const float*)d_in[3];
    const float* Wqkv  = (const float*)d_in[4];
    const float* Wproj = (const float*)d_in[5];
    const float* g2    = (const float*)d_in[6];
    const float* Wg    = (const float*)d_in[7];
    const float* Wu    = (const float*)d_in[8];
    const float* Wd    = (const float*)d_in[9];
    const float* gf    = (const float*)d_in[10];
    const float* Wlm   = (const float*)d_in[11];
    float* out = (float*)d_out;

    float *px, *ph, *pqkv, *py, *pg;
    cudaGetSymbolAddress((void**)&px,   g_x);
    cudaGetSymbolAddress((void**)&ph,   g_h);
    cudaGetSymbolAddress((void**)&pqkv, g_qkv);
    cudaGetSymbolAddress((void**)&py,   g_y);
    cudaGetSymbolAddress((void**)&pg,   g_gate);

    const int smem_bytes = SMEM_FLOATS * sizeof(float);  // 75776
    cudaFuncSetAttribute(gemm_tc<0, false>,
        cudaFuncAttributeMaxDynamicSharedMemorySize, smem_bytes);
    cudaFuncSetAttribute(gemm_tc<1, false>,
        cudaFuncAttributeMaxDynamicSharedMemorySize, smem_bytes);
    cudaFuncSetAttribute(gemm_tc<2, false>,
        cudaFuncAttributeMaxDynamicSharedMemorySize, smem_bytes);
    cudaFuncSetAttribute(gemm_tc<0, true>,
        cudaFuncAttributeMaxDynamicSharedMemorySize, smem_bytes);

    embed_kernel<<<MTOK, 256>>>(idx, wte, wpe, px);

    for (int l = 0; l < NL; l++) {
        rmsnorm_kernel<<<MTOK, 256>>>(px, g1 + (size_t)l * ND, ph);
        gemm_tc<0, false><<<dim3(3 * ND / 128, MTOK / 128), 256, smem_bytes>>>(
            ph, Wqkv + (size_t)l * ND * 3 * ND, nullptr, pqkv, MTOK, 3 * ND, ND);
        attn_kernel<<<dim3(NB * NH, NS / 128), 128>>>(pqkv, py);
        gemm_tc<1, false><<<dim3(ND / 128, MTOK / 128), 256, smem_bytes>>>(
            py, Wproj + (size_t)l * ND * ND, px, px, MTOK, ND, ND);
        rmsnorm_kernel<<<MTOK, 256>>>(px, g2 + (size_t)l * ND, ph);
        gemm_tc<0, false><<<dim3(NHID / 128, MTOK / 128), 256, smem_bytes>>>(
            ph, Wg + (size_t)l * ND * NHID, nullptr, pg, MTOK, NHID, ND);
        gemm_tc<2, false><<<dim3(NHID / 128, MTOK / 128), 256, smem_bytes>>>(
            ph, Wu + (size_t)l * ND * NHID, pg, pg, MTOK, NHID, ND);
        gemm_tc<1, false><<<dim3(ND / 128, MTOK / 128), 256, smem_bytes>>>(
            pg, Wd + (size_t)l * NHID * ND, px, px, MTOK, ND, NHID);
    }

    rmsnorm_kernel<<<MTOK, 256>>>(px, gf, ph);
    gemm_tc<0, true><<<dim3((NV + 127) / 128, MTOK / 128), 256, smem_bytes>>>(
        ph, Wlm, nullptr, out, MTOK, NV, ND);
}

// round 6
// speedup vs baseline: 2.4621x; 2.0178x over previous
#include <cuda_runtime.h>
#include <math.h>
#include <stdint.h>

// Problem constants
#define NB   2
#define NS   1024
#define ND   1024
#define NH   16
#define NDH  64
#define NL   12
#define NHID 2816
#define NV   50257
#define MTOK 2048   // NB*NS

// GEMM tiling: 128x128 block, BK=16, 8 warps (4m x 2n), warp tile 32x64
#define BM 128
#define BN 128
#define BK 16

// ---------------- scratch buffers ----------------
__device__ float g_x[MTOK * ND];
__device__ float g_h[MTOK * ND];
__device__ float g_qkv[MTOK * 3 * ND];
__device__ float g_y[MTOK * ND];
__device__ float g_gate[MTOK * NHID];

// ---------------- helpers ----------------
// A tile smem: 128 rows x 16 bf16 (32B/row), chunk-swizzled for LDSM
__device__ __forceinline__ uint32_t a_off(int m, int k) {
    uint32_t chunk = ((uint32_t)(k >> 3) ^ ((uint32_t)(m >> 2) & 1u)) & 1u;
    return (uint32_t)m * 32u + chunk * 16u + (uint32_t)(k & 7) * 2u;
}
// B tile smem: 16 rows x 128 bf16 (256B/row), chunk-swizzled for LDSM.trans
__device__ __forceinline__ uint32_t b_off(int k, int n) {
    uint32_t nb = (uint32_t)(n >> 3);
    uint32_t chunk = (nb & 8u) | ((nb ^ ((uint32_t)k & 7u)) & 7u);
    return (uint32_t)k * 256u + chunk * 16u + (uint32_t)(n & 7) * 2u;
}

__device__ __forceinline__ void ldsm4(uint32_t* r, uint32_t addr) {
    asm volatile("ldmatrix.sync.aligned.m8n8.x4.shared.b16 {%0,%1,%2,%3}, [%4];"
        : "=r"(r[0]), "=r"(r[1]), "=r"(r[2]), "=r"(r[3]) : "r"(addr));
}
__device__ __forceinline__ void ldsm4t(uint32_t* r, uint32_t addr) {
    asm volatile("ldmatrix.sync.aligned.m8n8.x4.trans.shared.b16 {%0,%1,%2,%3}, [%4];"
        : "=r"(r[0]), "=r"(r[1]), "=r"(r[2]), "=r"(r[3]) : "r"(addr));
}
#define MMA_BF16(acc, a, b0, b1)                                              \
    asm volatile(                                                              \
        "mma.sync.aligned.m16n8k16.row.col.f32.bf16.bf16.f32 "                 \
        "{%0,%1,%2,%3}, {%4,%5,%6,%7}, {%8,%9}, {%0,%1,%2,%3};"                \
        : "+f"(acc[0]), "+f"(acc[1]), "+f"(acc[2]), "+f"(acc[3])               \
        : "r"(a[0]), "r"(a[1]), "r"(a[2]), "r"(a[3]), "r"(b0), "r"(b1))

// split float4 into bf16x4 hi (rn) + lo (rn of residual); packed low=first elem
__device__ __forceinline__ void split4(float4 v, uint2& hi, uint2& lo) {
    uint32_t h0, h1, l0, l1;
    asm("cvt.rn.bf16x2.f32 %0, %1, %2;" : "=r"(h0) : "f"(v.y), "f"(v.x));
    asm("cvt.rn.bf16x2.f32 %0, %1, %2;" : "=r"(h1) : "f"(v.w), "f"(v.z));
    float hx = __uint_as_float(h0 << 16);
    float hy = __uint_as_float(h0 & 0xffff0000u);
    float hz = __uint_as_float(h1 << 16);
    float hw = __uint_as_float(h1 & 0xffff0000u);
    float lx = v.x - hx, ly = v.y - hy, lz = v.z - hz, lw = v.w - hw;
    asm("cvt.rn.bf16x2.f32 %0, %1, %2;" : "=r"(l0) : "f"(ly), "f"(lx));
    asm("cvt.rn.bf16x2.f32 %0, %1, %2;" : "=r"(l1) : "f"(lw), "f"(lz));
    hi.x = h0; hi.y = h1; lo.x = l0; lo.y = l1;
}

// ---------------- embedding ----------------
__global__ void embed_kernel(const int* __restrict__ idx,
                             const float* __restrict__ wte,
                             const float* __restrict__ wpe,
                             float* __restrict__ x) {
    int row = blockIdx.x;
    int t = threadIdx.x;
    int tok = idx[row];
    int spos = row & (NS - 1);
    float4 a = ((const float4*)(wte + (size_t)tok * ND))[t];
    float4 b = ((const float4*)(wpe + (size_t)spos * ND))[t];
    float4 o;
    o.x = a.x + b.x; o.y = a.y + b.y; o.z = a.z + b.z; o.w = a.w + b.w;
    ((float4*)(x + (size_t)row * ND))[t] = o;
}

// ---------------- rmsnorm ----------------
__global__ void rmsnorm_kernel(const float* __restrict__ in,
                               const float* __restrict__ gamma,
                               float* __restrict__ out) {
    int row = blockIdx.x;
    int t = threadIdx.x;
    float4 v = ((const float4*)(in + (size_t)row * ND))[t];
    float ss = v.x * v.x + v.y * v.y + v.z * v.z + v.w * v.w;
    #pragma unroll
    for (int off = 16; off; off >>= 1)
        ss += __shfl_xor_sync(0xFFFFFFFFu, ss, off);
    __shared__ float red[8];
    if ((t & 31) == 0) red[t >> 5] = ss;
    __syncthreads();
    float tot = red[0] + red[1] + red[2] + red[3] +
                red[4] + red[5] + red[6] + red[7];
    float r = rsqrtf(tot * (1.0f / (float)ND) + 1e-12f);
    float4 g = ((const float4*)gamma)[t];
    float4 o;
    o.x = v.x * r * g.x; o.y = v.y * r * g.y;
    o.z = v.z * r * g.z; o.w = v.w * r * g.w;
    ((float4*)(out + (size_t)row * ND))[t] = o;
}

// ---------------- bf16-split tensor-core GEMM with fused epilogues ----------
// C[M,N] = epi(A[M,K] @ B[K,N]);  EPI 0: acc; 1: X+acc; 2: silu(X)*acc
template<int EPI, bool NG>
__global__ __launch_bounds__(256, 2)
void gemm_bf(const float* __restrict__ A, const float* __restrict__ B,
             const float* __restrict__ X, float* __restrict__ C,
             int M, int N, int K) {
    // per buffer: Ah 4KB | Al 4KB | Bh 4KB | Bl 4KB  -> 16KB; double buffered
    __shared__ __align__(16) char sm[2 * 16384];
    const uint32_t sb = (uint32_t)__cvta_generic_to_shared(sm);

    const int tid  = threadIdx.x;
    const int lane = tid & 31;
    const int warp = tid >> 5;
    const int wm = warp & 3;        // 0..3
    const int wn = warp >> 2;       // 0..1
    const int lq = lane >> 2;       // 0..7
    const int lr = lane & 3;        // 0..3
    const int m0 = blockIdx.y * BM;
    const int n0 = blockIdx.x * BN;

    float c[2][8][4];
    #pragma unroll
    for (int i = 0; i < 2; i++)
        #pragma unroll
        for (int j = 0; j < 8; j++)
            #pragma unroll
            for (int k = 0; k < 4; k++) c[i][j][k] = 0.0f;

    // gmem load indexing (2 float4 per operand per thread)
    // A: li = tid + i*256 : m = li>>2, k0 = (li&3)*4
    // B: li = tid + i*256 : k = li>>5, n0b = (li&31)*4
    float4 aS[2], bS[2];

    auto gload = [&](int kt) {
        const int kbase = kt * BK;
        #pragma unroll
        for (int i = 0; i < 2; i++) {
            int li = tid + i * 256;
            int m = li >> 2, k0 = (li & 3) * 4;
            aS[i] = *(const float4*)(A + (size_t)(m0 + m) * K + kbase + k0);
        }
        #pragma unroll
        for (int i = 0; i < 2; i++) {
            int li = tid + i * 256;
            int k = li >> 5, nb = (li & 31) * 4;
            if (!NG) {
                bS[i] = *(const float4*)(B + (size_t)(kbase + k) * N + n0 + nb);
            } else {
                const float* bp = B + (size_t)(kbase + k) * N;
                int n = n0 + nb;
                float t0 = (n + 0 < N) ? bp[n + 0] : 0.0f;
                float t1 = (n + 1 < N) ? bp[n + 1] : 0.0f;
                float t2 = (n + 2 < N) ? bp[n + 2] : 0.0f;
                float t3 = (n + 3 < N) ? bp[n + 3] : 0.0f;
                bS[i] = make_float4(t0, t1, t2, t3);
            }
        }
    };

    auto sstore = [&](int buf) {
        char* base = sm + buf * 16384;
        #pragma unroll
        for (int i = 0; i < 2; i++) {
            int li = tid + i * 256;
            int m = li >> 2, k0 = (li & 3) * 4;
            uint2 hi, lo;
            split4(aS[i], hi, lo);
            uint32_t off = a_off(m, k0);
            *(uint2*)(base + off)        = hi;
            *(uint2*)(base + 4096 + off) = lo;
        }
        #pragma unroll
        for (int i = 0; i < 2; i++) {
            int li = tid + i * 256;
            int k = li >> 5, nb = (li & 31) * 4;
            uint2 hi, lo;
            split4(bS[i], hi, lo);
            uint32_t off = b_off(k, nb);
            *(uint2*)(base + 8192 + off)  = hi;
            *(uint2*)(base + 12288 + off) = lo;
        }
    };

    // lane-invariant pieces of LDSM addressing
    const int lid8 = lane >> 3;      // matrix id 0..3
    const int lrow = lane & 7;       // row within matrix

    auto compute = [&](int buf) {
        const uint32_t ah_base = sb + (uint32_t)buf * 16384u;
        const uint32_t al_base = ah_base + 4096u;
        const uint32_t bh_base = ah_base + 8192u;
        const uint32_t bl_base = ah_base + 12288u;

        // A fragments: for mf tile, matrices (m0-7,k0)(m8-15,k0)(m0-7,k8)(m8-15,k8)
        uint32_t ah[2][4], al[2][4];
        {
            int m = ((lid8 & 1) << 3) + lrow;     // row within 16
            int k = (lid8 >> 1) << 3;             // 0 or 8
            #pragma unroll
            for (int mf = 0; mf < 2; mf++) {
                uint32_t off = a_off(wm * 32 + mf * 16 + m, k);
                ldsm4(ah[mf], ah_base + off);
                ldsm4(al[mf], al_base + off);
            }
        }
        // B fragments + MMA in two halves of 4 n8-blocks
        #pragma unroll
        for (int h = 0; h < 2; h++) {
            uint32_t bhf[4][2], blf[4][2];
            #pragma unroll
            for (int j = 0; j < 2; j++) {
                int k  = ((lid8 & 1) << 3) + lrow;
                int nb = wn * 8 + h * 4 + j * 2 + (lid8 >> 1);
                uint32_t off = b_off(k, nb << 3);
                uint32_t rr[4];
                ldsm4t(rr, bh_base + off);
                bhf[j * 2][0] = rr[0]; bhf[j * 2][1] = rr[1];
                bhf[j * 2 + 1][0] = rr[2]; bhf[j * 2 + 1][1] = rr[3];
                ldsm4t(rr, bl_base + off);
                blf[j * 2][0] = rr[0]; blf[j * 2][1] = rr[1];
                blf[j * 2 + 1][0] = rr[2]; blf[j * 2 + 1][1] = rr[3];
            }
            #pragma unroll
            for (int mf = 0; mf < 2; mf++)
                #pragma unroll
                for (int j = 0; j < 4; j++) {
                    int nf = h * 4 + j;
                    MMA_BF16(c[mf][nf], ah[mf], bhf[j][0], bhf[j][1]);
                    MMA_BF16(c[mf][nf], ah[mf], blf[j][0], blf[j][1]);
                    MMA_BF16(c[mf][nf], al[mf], bhf[j][0], bhf[j][1]);
                }
        }
    };

    // ---- main loop ----
    const int ntk = K / BK;
    gload(0);
    sstore(0);
    __syncthreads();
    int cur = 0;
    for (int kt = 0; kt < ntk; kt++) {
        if (kt + 1 < ntk) gload(kt + 1);
        compute(cur);
        if (kt + 1 < ntk) {
            sstore(cur ^ 1);
            __syncthreads();
            cur ^= 1;
        }
    }

    // ---- epilogue ----
    #pragma unroll
    for (int mf = 0; mf < 2; mf++) {
        int r0 = m0 + wm * 32 + mf * 16 + lq;
        int r1 = r0 + 8;
        #pragma unroll
        for (int nf = 0; nf < 8; nf++) {
            int col = n0 + wn * 64 + nf * 8 + 2 * lr;
            if (!NG) {
                size_t o0 = (size_t)r0 * N + col;
                size_t o1 = (size_t)r1 * N + col;
                float2 v0 = make_float2(c[mf][nf][0], c[mf][nf][1]);
                float2 v1 = make_float2(c[mf][nf][2], c[mf][nf][3]);
                if (EPI == 1) {
                    float2 x0 = *(const float2*)(X + o0);
                    float2 x1 = *(const float2*)(X + o1);
                    v0.x += x0.x; v0.y += x0.y; v1.x += x1.x; v1.y += x1.y;
                } else if (EPI == 2) {
                    float2 x0 = *(const float2*)(X + o0);
                    float2 x1 = *(const float2*)(X + o1);
                    v0.x *= x0.x / (1.0f + __expf(-x0.x));
                    v0.y *= x0.y / (1.0f + __expf(-x0.y));
                    v1.x *= x1.x / (1.0f + __expf(-x1.x));
                    v1.y *= x1.y / (1.0f + __expf(-x1.y));
                }
                *(float2*)(C + o0) = v0;
                *(float2*)(C + o1) = v1;
            } else {
                #pragma unroll
                for (int e = 0; e < 2; e++) {
                    int n = col + e;
                    if (n < N) {
                        size_t o0 = (size_t)r0 * N + n;
                        size_t o1 = (size_t)r1 * N + n;
                        float v0 = c[mf][nf][e];
                        float v1 = c[mf][nf][2 + e];
                        if (EPI == 1) { v0 += X[o0]; v1 += X[o1]; }
                        else if (EPI == 2) {
                            float x0 = X[o0], x1 = X[o1];
                            v0 *= x0 / (1.0f + __expf(-x0));
                            v1 *= x1 / (1.0f + __expf(-x1));
                        }
                        C[o0] = v0; C[o1] = v1;
                    }
                }
            }
        }
    }
}

// ---------------- flash attention (causal, fp32) ----------------
__global__ __launch_bounds__(128)
void attn_kernel(const float* __restrict__ qkv, float* __restrict__ y) {
    const int bh = blockIdx.x;
    const int b  = bh >> 4;
    const int hh = bh & 15;
    const int qy = blockIdx.y;
    const int tid = threadIdx.x;
    const int qrow = qy * 128 + tid;

    const float* qptr = qkv + ((size_t)(b * NS + qrow) * (3 * ND)) + hh * NDH;
    float q[NDH];
    #pragma unroll
    for (int i = 0; i < 16; i++)
        *(float4*)&q[i * 4] = *(const float4*)(qptr + i * 4);

    float o[NDH];
    #pragma unroll
    for (int d = 0; d < NDH; d++) o[d] = 0.0f;
    float m = -1e30f, l = 0.0f;

    __shared__ float ksm[64][64];
    __shared__ float vsm[64][64];

    const int ntiles = (qy + 1) * 2;
    for (int kt = 0; kt < ntiles; kt++) {
        const int kbase = kt * 64;
        #pragma unroll
        for (int i = 0; i < 8; i++) {
            int li = tid + i * 128;
            int r  = li >> 4;
            int c4 = (li & 15) * 4;
            const float* base = qkv + ((size_t)(b * NS + kbase + r) * (3 * ND))
                                + hh * NDH + c4;
            *(float4*)&ksm[r][c4] = *(const float4*)(base + ND);
            *(float4*)&vsm[r][c4] = *(const float4*)(base + 2 * ND);
        }
        __syncthreads();

        if (qrow >= kbase) {
            #pragma unroll 1
            for (int jt = 0; jt < 4; jt++) {
                float s[16];
                #pragma unroll
                for (int j = 0; j < 16; j++) {
                    int key = kbase + jt * 16 + j;
                    if (key <= qrow) {
                        float a = 0.0f;
                        const float4* kr = (const float4*)ksm[jt * 16 + j];
                        #pragma unroll
                        for (int d4 = 0; d4 < 16; d4++) {
                            float4 kv = kr[d4];
                            a += q[d4 * 4 + 0] * kv.x + q[d4 * 4 + 1] * kv.y
                               + q[d4 * 4 + 2] * kv.z + q[d4 * 4 + 3] * kv.w;
                        }
                        s[j] = a * 0.125f;
                    } else {
                        s[j] = -1e30f;
                    }
                }
                float tm = s[0];
                #pragma unroll
                for (int j = 1; j < 16; j++) tm = fmaxf(tm, s[j]);
                float mnew = fmaxf(m, tm);
                float corr = __expf(m - mnew);
                float psum = 0.0f;
                #pragma unroll
                for (int j = 0; j < 16; j++) {
                    s[j] = __expf(s[j] - mnew);
                    psum += s[j];
                }
                l = l * corr + psum;
                m = mnew;
                #pragma unroll
                for (int d = 0; d < NDH; d++) o[d] *= corr;
                #pragma unroll
                for (int j = 0; j < 16; j++) {
                    float p = s[j];
                    const float4* vr = (const float4*)vsm[jt * 16 + j];
                    #pragma unroll
                    for (int d4 = 0; d4 < 16; d4++) {
                        float4 vv = vr[d4];
                        o[d4 * 4 + 0] += p * vv.x;
                        o[d4 * 4 + 1] += p * vv.y;
                        o[d4 * 4 + 2] += p * vv.z;
                        o[d4 * 4 + 3] += p * vv.w;
                    }
                }
            }
        }
        __syncthreads();
    }

    float inv = 1.0f / l;
    float* yp = y + ((size_t)(b * NS + qrow) * ND) + hh * NDH;
    #pragma unroll
    for (int i = 0; i < 16; i++) {
        float4 st;
        st.x = o[i * 4 + 0] * inv; st.y = o[i * 4 + 1] * inv;
        st.z = o[i * 4 + 2] * inv; st.w = o[i * 4 + 3] * inv;
        *(float4*)(yp + i * 4) = st;
    }
}

// ---------------- launch ----------------
extern "C" void kernel_launch(void* const* d_in, const int* in_sizes, int n_in,
                              void* d_out, int out_size) {
    const int*   idx   = (const int*)  d_in[0];
    const float* wte   = (const float*)d_in[1];
    const float* wpe   = (const float*)d_in[2];
    const float* g1    = (const float*)d_in[3];
    const float* Wqkv  = (const float*)d_in[4];
    const float* Wproj = (const float*)d_in[5];
    const float* g2    = (const float*)d_in[6];
    const float* Wg    = (const float*)d_in[7];
    const float* Wu    = (const float*)d_in[8];
    const float* Wd    = (const float*)d_in[9];
    const float* gf    = (const float*)d_in[10];
    const float* Wlm   = (const float*)d_in[11];
    float* out = (float*)d_out;

    float *px, *ph, *pqkv, *py, *pg;
    cudaGetSymbolAddress((void**)&px,   g_x);
    cudaGetSymbolAddress((void**)&ph,   g_h);
    cudaGetSymbolAddress((void**)&pqkv, g_qkv);
    cudaGetSymbolAddress((void**)&py,   g_y);
    cudaGetSymbolAddress((void**)&pg,   g_gate);

    embed_kernel<<<MTOK, 256>>>(idx, wte, wpe, px);

    for (int l = 0; l < NL; l++) {
        rmsnorm_kernel<<<MTOK, 256>>>(px, g1 + (size_t)l * ND, ph);
        gemm_bf<0, false><<<dim3(3 * ND / BN, MTOK / BM), 256>>>(
            ph, Wqkv + (size_t)l * ND * 3 * ND, nullptr, pqkv, MTOK, 3 * ND, ND);
        attn_kernel<<<dim3(NB * NH, NS / 128), 128>>>(pqkv, py);
        gemm_bf<1, false><<<dim3(ND / BN, MTOK / BM), 256>>>(
            py, Wproj + (size_t)l * ND * ND, px, px, MTOK, ND, ND);
        rmsnorm_kernel<<<MTOK, 256>>>(px, g2 + (size_t)l * ND, ph);
        gemm_bf<0, false><<<dim3(NHID / BN, MTOK / BM), 256>>>(
            ph, Wg + (size_t)l * ND * NHID, nullptr, pg, MTOK, NHID, ND);
        gemm_bf<2, false><<<dim3(NHID / BN, MTOK / BM), 256>>>(
            ph, Wu + (size_t)l * ND * NHID, pg, pg, MTOK, NHID, ND);
        gemm_bf<1, false><<<dim3(ND / BN, MTOK / BM), 256>>>(
            pg, Wd + (size_t)l * NHID * ND, px, px, MTOK, ND, NHID);
    }

    rmsnorm_kernel<<<MTOK, 256>>>(px, gf, ph);
    gemm_bf<0, true><<<dim3((NV + BN - 1) / BN, MTOK / BM), 256>>>(
        ph, Wlm, nullptr, out, MTOK, NV, ND);
}